// round 1
// baseline (speedup 1.0000x reference)
#include <cuda_runtime.h>
#include <math.h>

#define TX 32
#define TY 8
#define ZCHUNK 32
#define NZ 128
#define NY 128
#define NX 128
#define NCH 2
#define NB 2
#define NTHREADS (TX*TY)

// total output elements for the mean: B * 1 * H * W * D = 2 * 128^3
#define INV_N (1.0f / 4194304.0f)

__global__ void gme_zero_kernel(float* out) {
    if (threadIdx.x == 0) out[0] = 0.0f;
}

// Compute the 7 xy-reduced plane partials at (tx,ty) from a (TY+2)x(TX+2) smem tile.
// Filters along x first: S=[1,2,1], U=[1,1,1], D=[-1,0,1]; then along y.
// P[0]=Sy(Dx) P[1]=Uy(Dx) P[2]=Dy(Sx) P[3]=Sy(Sx) P[4]=Uy(Sx) P[5]=Dy(Ux) P[6]=Sy(Ux)
__device__ __forceinline__ void compute_p(const float t[TY+2][TX+2],
                                          int tx, int ty, float P[7]) {
    float sx[3], ux[3], dxv[3];
#pragma unroll
    for (int dy = 0; dy < 3; ++dy) {
        float aL = t[ty + dy][tx];
        float aC = t[ty + dy][tx + 1];
        float aR = t[ty + dy][tx + 2];
        float s  = aL + aR;
        sx[dy]  = s + 2.0f * aC;
        ux[dy]  = s + aC;
        dxv[dy] = aR - aL;
    }
    P[0] = dxv[0] + 2.0f * dxv[1] + dxv[2];
    P[1] = dxv[0] + dxv[1] + dxv[2];
    P[2] = sx[2] - sx[0];
    float t2 = sx[0] + sx[2];
    P[3] = t2 + 2.0f * sx[1];
    P[4] = t2 + sx[1];
    P[5] = ux[2] - ux[0];
    P[6] = ux[0] + 2.0f * ux[1] + ux[2];
}

// Load plane z of both inputs (channel-summed) into smem with zero halo,
// then compute the 7 partials per input. z outside [0,NZ) -> all zeros.
__device__ __forceinline__ void plane(
    int z, float tile[2][TY+2][TX+2],
    const float* __restrict__ yb, const float* __restrict__ pb,
    int gx0, int gy0, int tx, int ty, int tid,
    float P[2][7])
{
    if ((unsigned)z >= (unsigned)NZ) {
#pragma unroll
        for (int j = 0; j < 2; ++j)
#pragma unroll
            for (int k = 0; k < 7; ++k) P[j][k] = 0.0f;
        return;
    }
    const long VOL = (long)NZ * NY * NX;
    __syncthreads();  // previous plane's smem reads done
#pragma unroll 2
    for (int i = tid; i < (TY + 2) * (TX + 2); i += NTHREADS) {
        int row = i / (TX + 2);
        int col = i - row * (TX + 2);
        int gy = gy0 - 1 + row;
        int gx = gx0 - 1 + col;
        float vy = 0.0f, vp = 0.0f;
        if ((unsigned)gy < (unsigned)NY && (unsigned)gx < (unsigned)NX) {
            long off = (long)z * (NY * NX) + (long)gy * NX + gx;
            vy = __ldg(yb + off) + __ldg(yb + off + VOL);
            vp = __ldg(pb + off) + __ldg(pb + off + VOL);
        }
        tile[0][row][col] = vy;
        tile[1][row][col] = vp;
    }
    __syncthreads();
    compute_p(tile[0], tx, ty, P[0]);
    compute_p(tile[1], tx, ty, P[1]);
}

__device__ __forceinline__ float edge_from_ring(const float Pm[7],
                                                const float Pc[7],
                                                const float Pn[7]) {
    // z filters: S over p1,p2,p3,p6 ; U over p1,p3 ; D over p4,p5,p7
    float ssd = Pm[0] + 2.0f * Pc[0] + Pn[0];
    float usd = Pm[0] + Pc[0] + Pn[0];
    float sud = Pm[1] + 2.0f * Pc[1] + Pn[1];
    float sds = Pm[2] + 2.0f * Pc[2] + Pn[2];
    float uds = Pm[2] + Pc[2] + Pn[2];
    float dss = Pn[3] - Pm[3];
    float dus = Pn[4] - Pm[4];
    float sdu = Pm[5] + 2.0f * Pc[5] + Pn[5];
    float dsu = Pn[6] - Pm[6];
    float ssq = ssd * ssd + sds * sds + dss * dss
              + 2.0f * (sud * sud + sdu * sdu + dus * dus
                        + uds * uds + usd * usd + dsu * dsu);
    // mag = sqrt(ssq + eps) / C, C = 2
    return sqrtf(ssq + 1e-12f) * 0.5f;
}

extern "C" __global__ void __launch_bounds__(NTHREADS)
gme3d_kernel(const float* __restrict__ y, const float* __restrict__ yp,
             float* __restrict__ out)
{
    __shared__ float tile[2][TY + 2][TX + 2];
    __shared__ float warpsum[NTHREADS / 32];

    const int tx = threadIdx.x;
    const int ty = threadIdx.y;
    const int tid = ty * TX + tx;
    const int gx0 = blockIdx.x * TX;
    const int gy0 = blockIdx.y * TY;
    const int NCHUNKS = NZ / ZCHUNK;
    const int b  = blockIdx.z / NCHUNKS;
    const int z0 = (blockIdx.z % NCHUNKS) * ZCHUNK;
    const long VOL = (long)NZ * NY * NX;
    const float* yb = y  + (long)b * NCH * VOL;
    const float* pb = yp + (long)b * NCH * VOL;

    float Pm[2][7], Pc[2][7], Pn[2][7];

    plane(z0 - 1, tile, yb, pb, gx0, gy0, tx, ty, tid, Pm);
    plane(z0,     tile, yb, pb, gx0, gy0, tx, ty, tid, Pc);

    float acc = 0.0f;
#pragma unroll 1
    for (int zo = z0; zo < z0 + ZCHUNK; ++zo) {
        plane(zo + 1, tile, yb, pb, gx0, gy0, tx, ty, tid, Pn);

        float ey = edge_from_ring(Pm[0], Pc[0], Pn[0]);
        float ep = edge_from_ring(Pm[1], Pc[1], Pn[1]);
        float d = ey - ep;
        acc += d * d;

#pragma unroll
        for (int j = 0; j < 2; ++j)
#pragma unroll
            for (int k = 0; k < 7; ++k) {
                Pm[j][k] = Pc[j][k];
                Pc[j][k] = Pn[j][k];
            }
    }

    // block reduction
#pragma unroll
    for (int o = 16; o; o >>= 1)
        acc += __shfl_down_sync(0xffffffffu, acc, o);
    if ((tid & 31) == 0) warpsum[tid >> 5] = acc;
    __syncthreads();
    if (tid == 0) {
        float s = 0.0f;
#pragma unroll
        for (int w = 0; w < NTHREADS / 32; ++w) s += warpsum[w];
        atomicAdd(out, s * INV_N);
    }
}

extern "C" void kernel_launch(void* const* d_in, const int* in_sizes, int n_in,
                              void* d_out, int out_size)
{
    const float* y  = (const float*)d_in[0];
    const float* yp = (const float*)d_in[1];
    float* out = (float*)d_out;

    gme_zero_kernel<<<1, 32>>>(out);

    dim3 grid(NX / TX, NY / TY, NB * (NZ / ZCHUNK));
    dim3 blk(TX, TY);
    gme3d_kernel<<<grid, blk>>>(y, yp, out);
}

// round 4
// speedup vs baseline: 1.1025x; 1.1025x over previous
#include <cuda_runtime.h>
#include <math.h>

#define TX 32
#define TY 8
#define ZCHUNK 16
#define NZ 128
#define NY 128
#define NX 128
#define NB 2
#define NTHREADS (TX*TY)
#define ROWS (TY+2)          // 10
#define COLS (TX+2)          // 34
#define TILE_N (ROWS*COLS)   // 340
#define VOL (NZ*NY*NX)       // one channel volume: 2097152
#define INV_N (1.0f/4194304.0f)

__global__ void gme_zero_kernel(float* out) {
    if (threadIdx.x == 0) out[0] = 0.0f;
}

struct FR { float y0, p0, y1, p1; };

// x-then-y separable partials from a raw plane tile (stride COLS).
// P[0]=Sy(Dx) P[1]=Uy(Dx) P[2]=Dy(Sx) P[3]=Sy(Sx) P[4]=Uy(Sx) P[5]=Dy(Ux) P[6]=Sy(Ux)
__device__ __forceinline__ void compute_p(const float* __restrict__ t,
                                          int tx, int ty, float P[7]) {
    float sx[3], ux[3], dxv[3];
#pragma unroll
    for (int dy = 0; dy < 3; ++dy) {
        const float* r = t + (ty + dy) * COLS + tx;
        float aL = r[0], aC = r[1], aR = r[2];
        float s = aL + aR;
        sx[dy] = s + 2.0f * aC;
        ux[dy] = s + aC;
        dxv[dy] = aR - aL;
    }
    P[0] = dxv[0] + 2.0f * dxv[1] + dxv[2];
    P[1] = dxv[0] + dxv[1] + dxv[2];
    P[2] = sx[2] - sx[0];
    float t2 = sx[0] + sx[2];
    P[3] = t2 + 2.0f * sx[1];
    P[4] = t2 + sx[1];
    P[5] = ux[2] - ux[0];
    P[6] = ux[0] + 2.0f * ux[1] + ux[2];
}

__device__ __forceinline__ float edge_mag(const float Pm[7], const float Pc[7],
                                          const float Pn[7]) {
    float ssd = Pm[0] + 2.0f * Pc[0] + Pn[0];
    float usd = Pm[0] + Pc[0] + Pn[0];
    float sud = Pm[1] + 2.0f * Pc[1] + Pn[1];
    float sds = Pm[2] + 2.0f * Pc[2] + Pn[2];
    float uds = Pm[2] + Pc[2] + Pn[2];
    float dss = Pn[3] - Pm[3];
    float dus = Pn[4] - Pm[4];
    float sdu = Pm[5] + 2.0f * Pc[5] + Pn[5];
    float dsu = Pn[6] - Pm[6];
    float ssq = ssd * ssd + sds * sds + dss * dss
              + 2.0f * (sud * sud + sdu * sdu + dus * dus
                        + uds * uds + usd * usd + dsu * dsu);
    return sqrtf(ssq + 1e-12f) * 0.5f;   // sqrt(ssq+eps)/C, C=2
}

// Fetch plane z (channel-summed, both tensors) into registers. z OOB -> zeros.
__device__ __forceinline__ void fetchz(int z,
                                       const float* __restrict__ yb,
                                       const float* __restrict__ pb,
                                       long off0, bool v0, long off1, bool v1,
                                       FR& f) {
    f.y0 = 0.0f; f.p0 = 0.0f; f.y1 = 0.0f; f.p1 = 0.0f;
    if ((unsigned)z < (unsigned)NZ) {
        long zb = (long)z * (NY * NX);
        if (v0) {
            f.y0 = __ldg(yb + zb + off0) + __ldg(yb + zb + off0 + VOL);
            f.p0 = __ldg(pb + zb + off0) + __ldg(pb + zb + off0 + VOL);
        }
        if (v1) {
            f.y1 = __ldg(yb + zb + off1) + __ldg(yb + zb + off1 + VOL);
            f.p1 = __ldg(pb + zb + off1) + __ldg(pb + zb + off1 + VOL);
        }
    }
}

__device__ __forceinline__ void storez(float* __restrict__ buf, int tid,
                                       bool has2, const FR& f) {
    buf[tid] = f.y0;
    buf[TILE_N + tid] = f.p0;
    if (has2) {
        buf[tid + NTHREADS] = f.y1;
        buf[TILE_N + tid + NTHREADS] = f.p1;
    }
}

// One z-step: store prefetched plane (zo+1), prefetch plane zo+2, sync,
// compute Pn for plane zo+1, emit output at plane zo.
__device__ __forceinline__ void stepf(int zo, float* __restrict__ tile, int tid,
                                      bool has2, int tx, int ty,
                                      const float* __restrict__ yb,
                                      const float* __restrict__ pb,
                                      long off0, bool v0, long off1, bool v1,
                                      FR& fr,
                                      float Pm[2][7], float Pc[2][7], float Pn[2][7],
                                      float& acc) {
    float* buf = tile + (size_t)((zo + 1) & 1) * (2 * TILE_N);
    storez(buf, tid, has2, fr);
    fetchz(zo + 2, yb, pb, off0, v0, off1, v1, fr);
    __syncthreads();
    compute_p(buf, tx, ty, Pn[0]);
    compute_p(buf + TILE_N, tx, ty, Pn[1]);
    float ey = edge_mag(Pm[0], Pc[0], Pn[0]);
    float ep = edge_mag(Pm[1], Pc[1], Pn[1]);
    float d = ey - ep;
    acc += d * d;
}

extern "C" __global__ void __launch_bounds__(NTHREADS, 4)
gme3d_kernel(const float* __restrict__ y, const float* __restrict__ yp,
             float* __restrict__ out)
{
    __shared__ float tile[2 * 2 * TILE_N];   // [buffer][input][idx]
    __shared__ float warpsum[NTHREADS / 32];

    const int tx = threadIdx.x;
    const int ty = threadIdx.y;
    const int tid = ty * TX + tx;
    const int gx0 = blockIdx.x * TX;
    const int gy0 = blockIdx.y * TY;
    const int b  = blockIdx.z >> 3;          // NZ/ZCHUNK = 8 chunks
    const int z0 = (blockIdx.z & 7) * ZCHUNK;

    const float* yb = y  + (long)b * 2 * VOL;
    const float* pb = yp + (long)b * 2 * VOL;

    // Precompute the two tile-fill offsets this thread owns.
    const int i0 = tid;
    const int r0 = i0 / COLS, c0 = i0 - r0 * COLS;
    const int gy_0 = gy0 - 1 + r0, gx_0 = gx0 - 1 + c0;
    const bool v0 = (unsigned)gy_0 < (unsigned)NY && (unsigned)gx_0 < (unsigned)NX;
    const long off0 = v0 ? ((long)gy_0 * NX + gx_0) : 0;

    const int i1 = tid + NTHREADS;
    const bool has2 = i1 < TILE_N;
    const int r1 = i1 / COLS, c1 = i1 - r1 * COLS;
    const int gy_1 = gy0 - 1 + r1, gx_1 = gx0 - 1 + c1;
    const bool v1 = has2 && (unsigned)gy_1 < (unsigned)NY && (unsigned)gx_1 < (unsigned)NX;
    const long off1 = v1 ? ((long)gy_1 * NX + gx_1) : 0;

    float PA[2][7], PB[2][7], PC[2][7];
    FR fr;

    // Prologue: planes z0-1 -> PA, z0 -> PB; leave plane z0+1 in fr.
    fetchz(z0 - 1, yb, pb, off0, v0, off1, v1, fr);
    {
        float* buf = tile + (size_t)((z0 - 1) & 1) * (2 * TILE_N);
        storez(buf, tid, has2, fr);
        fetchz(z0, yb, pb, off0, v0, off1, v1, fr);
        __syncthreads();
        compute_p(buf, tx, ty, PA[0]);
        compute_p(buf + TILE_N, tx, ty, PA[1]);
    }
    {
        float* buf = tile + (size_t)(z0 & 1) * (2 * TILE_N);
        storez(buf, tid, has2, fr);
        fetchz(z0 + 1, yb, pb, off0, v0, off1, v1, fr);
        __syncthreads();
        compute_p(buf, tx, ty, PB[0]);
        compute_p(buf + TILE_N, tx, ty, PB[1]);
    }

    // Main loop: 16 z-steps = 5 register-rotated triples + 1 tail step.
    float acc = 0.0f;
    int zo = z0;
#pragma unroll 1
    for (int it = 0; it < 5; ++it) {
        stepf(zo,     tile, tid, has2, tx, ty, yb, pb, off0, v0, off1, v1, fr, PA, PB, PC, acc);
        stepf(zo + 1, tile, tid, has2, tx, ty, yb, pb, off0, v0, off1, v1, fr, PB, PC, PA, acc);
        stepf(zo + 2, tile, tid, has2, tx, ty, yb, pb, off0, v0, off1, v1, fr, PC, PA, PB, acc);
        zo += 3;
    }
    stepf(zo, tile, tid, has2, tx, ty, yb, pb, off0, v0, off1, v1, fr, PA, PB, PC, acc);

    // Block reduction -> single atomic.
#pragma unroll
    for (int o = 16; o; o >>= 1)
        acc += __shfl_down_sync(0xffffffffu, acc, o);
    if ((tid & 31) == 0) warpsum[tid >> 5] = acc;
    __syncthreads();
    if (tid == 0) {
        float s = 0.0f;
#pragma unroll
        for (int w = 0; w < NTHREADS / 32; ++w) s += warpsum[w];
        atomicAdd(out, s * INV_N);
    }
}

extern "C" void kernel_launch(void* const* d_in, const int* in_sizes, int n_in,
                              void* d_out, int out_size)
{
    const float* y  = (const float*)d_in[0];
    const float* yp = (const float*)d_in[1];
    float* out = (float*)d_out;

    gme_zero_kernel<<<1, 32>>>(out);

    dim3 grid(NX / TX, NY / TY, NB * (NZ / ZCHUNK));
    dim3 blk(TX, TY);
    gme3d_kernel<<<grid, blk>>>(y, yp, out);
}

// round 9
// speedup vs baseline: 1.2609x; 1.1436x over previous
#include <cuda_runtime.h>
#include <math.h>

#define TX 32
#define TY 8
#define ZC 8
#define NZ 128
#define NY 128
#define NX 128
#define NB 2
#define NTHREADS 256
#define XSPAN 64                 // VX=2 * TX
#define ROWS (TY+2)              // 10
#define FCOLS 68                 // padded float cols (66 used)
#define UCOLS 34                 // ull cols per row
#define ENT1 660                 // 10*66 entries per input
#define ENTT 1320                // both inputs
#define VOL (NZ*NY*NX)
#define INV_N (1.0f/4194304.0f)
#define EPS 1e-12f

typedef unsigned long long ull;

__device__ __forceinline__ ull add2(ull a, ull b) {
    ull r; asm("add.rn.f32x2 %0,%1,%2;" : "=l"(r) : "l"(a), "l"(b)); return r;
}
__device__ __forceinline__ ull mul2(ull a, ull b) {
    ull r; asm("mul.rn.f32x2 %0,%1,%2;" : "=l"(r) : "l"(a), "l"(b)); return r;
}
__device__ __forceinline__ ull fma2(ull a, ull b, ull c) {
    ull r; asm("fma.rn.f32x2 %0,%1,%2,%3;" : "=l"(r) : "l"(a), "l"(b), "l"(c)); return r;
}
#define TWO2  0x4000000040000000ULL
#define NEG12 0xBF800000BF800000ULL
__device__ __forceinline__ ull sub2(ull a, ull b) {  // a - b
    return fma2(b, NEG12, a);
}
__device__ __forceinline__ ull packmid(ull p, ull q) {
    // lanes: lo = hi(p), hi = lo(q)  -> center taps (X0, X1)
    unsigned int ph = (unsigned int)(p >> 32);
    unsigned int ql = (unsigned int)q;
    ull r; asm("mov.b64 %0, {%1,%2};" : "=l"(r) : "r"(ph), "r"(ql)); return r;
}

__global__ void gme_zero_kernel(float* out) {
    if (threadIdx.x == 0) out[0] = 0.0f;
}

// Fresh partials N from tile rows + edge ssq from (M, C, N); writes N into M.
__device__ __forceinline__ ull edge_step(const ull* __restrict__ tbase,
                                         int tx, int ty, ull* M, const ull* C) {
    ull sx[3], ux[3], dx[3];
#pragma unroll
    for (int r = 0; r < 3; ++r) {
        const ull* row = tbase + (ty + r) * UCOLS;
        ull p = row[tx];
        ull q = row[tx + 1];
        ull cm = packmid(p, q);
        ull e = add2(p, q);
        sx[r] = fma2(cm, TWO2, e);
        ux[r] = add2(e, cm);
        dx[r] = sub2(q, p);
    }
    ull t, N0, N1, N2, N3, N4, N5, N6;
    t = add2(dx[0], dx[2]); N0 = fma2(dx[1], TWO2, t); N1 = add2(t, dx[1]);
    N2 = sub2(sx[2], sx[0]);
    t = add2(sx[0], sx[2]); N3 = fma2(sx[1], TWO2, t); N4 = add2(t, sx[1]);
    N5 = sub2(ux[2], ux[0]);
    t = add2(ux[0], ux[2]); N6 = fma2(ux[1], TWO2, t);

    ull a;
    a = add2(M[0], N0); ull ssd = fma2(C[0], TWO2, a); ull usd = add2(a, C[0]);
    a = add2(M[1], N1); ull sud = fma2(C[1], TWO2, a);   // S_z combine (2x center)
    a = add2(M[2], N2); ull sds = fma2(C[2], TWO2, a); ull uds = add2(a, C[2]);
    ull dss = sub2(N3, M[3]);
    ull dus = sub2(N4, M[4]);
    a = add2(M[5], N5); ull sdu = fma2(C[5], TWO2, a);
    ull dsu = sub2(N6, M[6]);

    ull s1 = mul2(ssd, ssd); s1 = fma2(sds, sds, s1); s1 = fma2(dss, dss, s1);
    ull s2 = mul2(sud, sud); s2 = fma2(sdu, sdu, s2); s2 = fma2(dus, dus, s2);
    s2 = fma2(uds, uds, s2); s2 = fma2(usd, usd, s2); s2 = fma2(dsu, dsu, s2);

    M[0] = N0; M[1] = N1; M[2] = N2; M[3] = N3; M[4] = N4; M[5] = N5; M[6] = N6;
    return fma2(s2, TWO2, s1);
}

// Prologue variant: partials only, into D.
__device__ __forceinline__ void partials_only(const ull* __restrict__ tbase,
                                              int tx, int ty, ull* D) {
    ull sx[3], ux[3], dx[3];
#pragma unroll
    for (int r = 0; r < 3; ++r) {
        const ull* row = tbase + (ty + r) * UCOLS;
        ull p = row[tx];
        ull q = row[tx + 1];
        ull cm = packmid(p, q);
        ull e = add2(p, q);
        sx[r] = fma2(cm, TWO2, e);
        ux[r] = add2(e, cm);
        dx[r] = sub2(q, p);
    }
    ull t;
    t = add2(dx[0], dx[2]); D[0] = fma2(dx[1], TWO2, t); D[1] = add2(t, dx[1]);
    D[2] = sub2(sx[2], sx[0]);
    t = add2(sx[0], sx[2]); D[3] = fma2(sx[1], TWO2, t); D[4] = add2(t, sx[1]);
    D[5] = sub2(ux[2], ux[0]);
    t = add2(ux[0], ux[2]); D[6] = fma2(ux[1], TWO2, t);
}

extern "C" __global__ void __launch_bounds__(NTHREADS, 2)
gme3d_kernel(const float* __restrict__ y, const float* __restrict__ yp,
             float* __restrict__ out)
{
    __shared__ ull tileU[2][2][ROWS * UCOLS];   // [parity][input][row*34 + ucol]
    __shared__ float warpsum[NTHREADS / 32];

    const int tx = threadIdx.x;
    const int ty = threadIdx.y;
    const int tid = ty * TX + tx;
    const int gx0 = blockIdx.x * XSPAN;
    const int gy0 = blockIdx.y * TY;
    const int b  = blockIdx.z >> 4;             // 16 z-chunks
    const int z0 = (blockIdx.z & 15) * ZC;

    const float* yb = y  + (size_t)b * 2 * VOL;
    const float* pb = yp + (size_t)b * 2 * VOL;

    // ---- precompute fill slots: 6 per thread over 1320 entries ----
    int goffk[6], soffk[6];
    const bool has6 = tid < (ENTT - 5 * NTHREADS);   // tid < 40
#pragma unroll
    for (int k = 0; k < 6; ++k) {
        int e = tid + k * NTHREADS;
        goffk[k] = -1; soffk[k] = 0;
        if (e < ENTT) {
            int inp = e >= ENT1;
            int e2 = e - inp * ENT1;
            int row = e2 / 66;
            int col = e2 - row * 66;
            soffk[k] = inp * (ROWS * FCOLS) + row * FCOLS + col;
            int gy = gy0 - 1 + row;
            int gx = gx0 - 1 + col;
            if ((unsigned)gy < (unsigned)NY && (unsigned)gx < (unsigned)NX)
                goffk[k] = (gy * NX + gx) | (inp << 30);
        }
    }

    float fr[6];
    // fetch plane pz into fr
    auto fetchz = [&](int pz) {
        const bool zok = (unsigned)pz < (unsigned)NZ;
        const int zb = pz * (NY * NX);
#pragma unroll
        for (int k = 0; k < 6; ++k) {
            float v = 0.0f;
            int g = goffk[k];
            if (zok && g >= 0) {
                int inp = g >> 30;
                int off = g & 0x3FFF;
                const float* s = (inp ? pb : yb) + (size_t)(zb + off);
                v = __ldg(s) + __ldg(s + VOL);
            }
            fr[k] = v;
        }
    };
    auto storez = [&](int par) {
        float* tf = (float*)&tileU[par][0][0];
#pragma unroll
        for (int k = 0; k < 5; ++k) tf[soffk[k]] = fr[k];
        if (has6) tf[soffk[5]] = fr[5];
    };

    ull R0[2][7], R1[2][7];    // ring arrays per input: role-swapped m/c

    // ---- prologue: plane z0-1 -> R0, plane z0 -> R1; fr ends with z0+1 ----
    fetchz(z0 - 1);
    storez(1);                          // (z0-1)&1 == 1 (z0 multiple of 8)
    fetchz(z0);
    __syncthreads();
    partials_only(&tileU[1][0][0], tx, ty, R0[0]);
    partials_only(&tileU[1][1][0], tx, ty, R0[1]);
    storez(0);
    fetchz(z0 + 1);
    __syncthreads();
    partials_only(&tileU[0][0][0], tx, ty, R1[0]);
    partials_only(&tileU[0][1][0], tx, ty, R1[1]);

    float acc = 0.0f;
    // one emission step: store fr (plane zo+1) -> buf[par], prefetch zo+2,
    // sync, fresh partials from buf[par], edge for both inputs, accumulate.
    auto emit = [&](int zo, int par, ull (*M)[7], ull (*C)[7]) {
        storez(par);
        fetchz(zo + 2);
        __syncthreads();
        ull sy = edge_step(&tileU[par][0][0], tx, ty, M[0], C[0]);
        ull sp = edge_step(&tileU[par][1][0], tx, ty, M[1], C[1]);
        float syA = __uint_as_float((unsigned int)sy);
        float syB = __uint_as_float((unsigned int)(sy >> 32));
        float spA = __uint_as_float((unsigned int)sp);
        float spB = __uint_as_float((unsigned int)(sp >> 32));
        float dA = sqrtf(syA + EPS) - sqrtf(spA + EPS);
        float dB = sqrtf(syB + EPS) - sqrtf(spB + EPS);
        acc = fmaf(dA, dA, acc);
        acc = fmaf(dB, dB, acc);
    };

    int zo = z0;
#pragma unroll 1
    for (int i = 0; i < ZC / 2; ++i) {
        emit(zo,     1, R0, R1);   // fresh overwrites R0; next m=R1, c=R0
        emit(zo + 1, 0, R1, R0);
        zo += 2;
    }

    // ---- reduction ----
#pragma unroll
    for (int o = 16; o; o >>= 1)
        acc += __shfl_down_sync(0xffffffffu, acc, o);
    if ((tid & 31) == 0) warpsum[tid >> 5] = acc;
    __syncthreads();
    if (tid == 0) {
        float s = 0.0f;
#pragma unroll
        for (int w = 0; w < NTHREADS / 32; ++w) s += warpsum[w];
        atomicAdd(out, s * (0.25f * INV_N));   // (1/2 per-mag scale)^2 * 1/N
    }
}

extern "C" void kernel_launch(void* const* d_in, const int* in_sizes, int n_in,
                              void* d_out, int out_size)
{
    const float* y  = (const float*)d_in[0];
    const float* yp = (const float*)d_in[1];
    float* out = (float*)d_out;

    gme_zero_kernel<<<1, 32>>>(out);

    dim3 grid(NX / XSPAN, NY / TY, NB * (NZ / ZC));   // 2 x 16 x 32
    dim3 blk(TX, TY);
    gme3d_kernel<<<grid, blk>>>(y, yp, out);
}

// round 11
// speedup vs baseline: 1.4617x; 1.1593x over previous
#include <cuda_runtime.h>
#include <math.h>

#define TX 32
#define TYT 4                    // tile data rows per input
#define ZC 8
#define NZ 128
#define NY 128
#define NX 128
#define NB 2
#define NTHREADS 256
#define HALF 128
#define XSPAN 64                 // 2 voxels per thread in x
#define ROWS 6                   // TYT+2
#define FCOLS 68                 // padded float cols (66 used)
#define UCOLS 34
#define TILE_ULL (ROWS*UCOLS)    // 204
#define ENT 396                  // 6*66 float entries per input
#define VOL (NZ*NY*NX)
#define INV_N (1.0f/4194304.0f)
#define EPS 1e-12f

typedef unsigned long long ull;

__device__ __forceinline__ ull add2(ull a, ull b) {
    ull r; asm("add.rn.f32x2 %0,%1,%2;" : "=l"(r) : "l"(a), "l"(b)); return r;
}
__device__ __forceinline__ ull mul2(ull a, ull b) {
    ull r; asm("mul.rn.f32x2 %0,%1,%2;" : "=l"(r) : "l"(a), "l"(b)); return r;
}
__device__ __forceinline__ ull fma2(ull a, ull b, ull c) {
    ull r; asm("fma.rn.f32x2 %0,%1,%2,%3;" : "=l"(r) : "l"(a), "l"(b), "l"(c)); return r;
}
#define TWO2  0x4000000040000000ULL
#define NEG12 0xBF800000BF800000ULL
__device__ __forceinline__ ull sub2(ull a, ull b) { return fma2(b, NEG12, a); }
__device__ __forceinline__ ull packmid(ull p, ull q) {
    unsigned int ph = (unsigned int)(p >> 32);
    unsigned int ql = (unsigned int)q;
    ull r; asm("mov.b64 %0, {%1,%2};" : "=l"(r) : "r"(ph), "r"(ql)); return r;
}
__device__ __forceinline__ float lo2(ull a) { return __uint_as_float((unsigned int)a); }
__device__ __forceinline__ float hi2(ull a) { return __uint_as_float((unsigned int)(a >> 32)); }
__device__ __forceinline__ ull mk2(float a, float b) {
    ull r; asm("mov.b64 %0, {%1,%2};" : "=l"(r) : "f"(a), "f"(b)); return r;
}

__global__ void gme_zero_kernel(float* out) {
    if (threadIdx.x == 0) out[0] = 0.0f;
}

// Fresh partials N from 3 tile rows; combine (M,C,N) -> packed ssq; N overwrites M.
__device__ __forceinline__ ull edge_step(const ull* __restrict__ t,
                                         int tx, int tyl, ull* M, const ull* C) {
    ull sx[3], ux[3], dx[3];
#pragma unroll
    for (int r = 0; r < 3; ++r) {
        const ull* row = t + (tyl + r) * UCOLS;
        ull p = row[tx];
        ull q = row[tx + 1];
        ull cm = packmid(p, q);
        ull e = add2(p, q);
        sx[r] = fma2(cm, TWO2, e);
        ux[r] = add2(e, cm);
        dx[r] = sub2(q, p);
    }
    ull t0, N0, N1, N2, N3, N4, N5, N6;
    t0 = add2(dx[0], dx[2]); N0 = fma2(dx[1], TWO2, t0); N1 = add2(t0, dx[1]);
    N2 = sub2(sx[2], sx[0]);
    t0 = add2(sx[0], sx[2]); N3 = fma2(sx[1], TWO2, t0); N4 = add2(t0, sx[1]);
    N5 = sub2(ux[2], ux[0]);
    t0 = add2(ux[0], ux[2]); N6 = fma2(ux[1], TWO2, t0);

    ull a;
    a = add2(M[0], N0); ull ssd = fma2(C[0], TWO2, a); ull usd = add2(a, C[0]);
    a = add2(M[1], N1); ull sud = fma2(C[1], TWO2, a);
    a = add2(M[2], N2); ull sds = fma2(C[2], TWO2, a); ull uds = add2(a, C[2]);
    ull dss = sub2(N3, M[3]);
    ull dus = sub2(N4, M[4]);
    a = add2(M[5], N5); ull sdu = fma2(C[5], TWO2, a);
    ull dsu = sub2(N6, M[6]);

    ull s1 = mul2(ssd, ssd); s1 = fma2(sds, sds, s1); s1 = fma2(dss, dss, s1);
    ull s2 = mul2(sud, sud); s2 = fma2(sdu, sdu, s2); s2 = fma2(dus, dus, s2);
    s2 = fma2(uds, uds, s2); s2 = fma2(usd, usd, s2); s2 = fma2(dsu, dsu, s2);

    M[0] = N0; M[1] = N1; M[2] = N2; M[3] = N3; M[4] = N4; M[5] = N5; M[6] = N6;
    return fma2(s2, TWO2, s1);
}

__device__ __forceinline__ void partials_only(const ull* __restrict__ t,
                                              int tx, int tyl, ull* D) {
    ull sx[3], ux[3], dx[3];
#pragma unroll
    for (int r = 0; r < 3; ++r) {
        const ull* row = t + (tyl + r) * UCOLS;
        ull p = row[tx];
        ull q = row[tx + 1];
        ull cm = packmid(p, q);
        ull e = add2(p, q);
        sx[r] = fma2(cm, TWO2, e);
        ux[r] = add2(e, cm);
        dx[r] = sub2(q, p);
    }
    ull t0;
    t0 = add2(dx[0], dx[2]); D[0] = fma2(dx[1], TWO2, t0); D[1] = add2(t0, dx[1]);
    D[2] = sub2(sx[2], sx[0]);
    t0 = add2(sx[0], sx[2]); D[3] = fma2(sx[1], TWO2, t0); D[4] = add2(t0, sx[1]);
    D[5] = sub2(ux[2], ux[0]);
    t0 = add2(ux[0], ux[2]); D[6] = fma2(ux[1], TWO2, t0);
}

extern "C" __global__ void __launch_bounds__(NTHREADS, 3)
gme3d_kernel(const float* __restrict__ y, const float* __restrict__ yp,
             float* __restrict__ out)
{
    __shared__ ull tileU[2][2][TILE_ULL];   // [parity][input][row*34+ucol]
    __shared__ ull exch[2][HALF];           // input1 magnitudes, by plane parity
    __shared__ float warpsum[NTHREADS / 32];

    const int tx  = threadIdx.x;
    const int ty  = threadIdx.y;            // 0..7
    const int tyl = ty & 3;                 // row within my input's tile
    const int inp = ty >> 2;                // 0: y, 1: yp
    const int tid = ty * TX + tx;
    const int t128 = tyl * TX + tx;         // 0..127 within input half
    const int gx0 = blockIdx.x * XSPAN;
    const int gy0 = blockIdx.y * TYT;
    const int b  = blockIdx.z >> 4;
    const int z0 = (blockIdx.z & 15) * ZC;

    const float* ib = (inp ? yp : y) + (size_t)b * 2 * VOL;

    // fill slots: up to 4 entries of my input's 396-float tile
    const bool has4 = t128 < (ENT - 3 * HALF);   // t128 < 12
    unsigned int pk[4];
#pragma unroll
    for (int k = 0; k < 4; ++k) {
        pk[k] = 0;
        int e = t128 + k * HALF;
        if (e < ENT) {
            int row = e / 66, col = e - row * 66;
            unsigned int v = (unsigned)((row * FCOLS + col) << 14);
            int gy = gy0 - 1 + row, gx = gx0 - 1 + col;
            if ((unsigned)gy < (unsigned)NY && (unsigned)gx < (unsigned)NX)
                v |= 0x80000000u | (unsigned)(gy * NX + gx);
            pk[k] = v;
        }
    }

    float fr[4];
    auto fetchz = [&](int pz) {
        const bool zok = (unsigned)pz < (unsigned)NZ;
        const int zb = pz * (NY * NX);
#pragma unroll
        for (int k = 0; k < 4; ++k) {
            float v = 0.0f;
            if (k < 3 || has4) {
                unsigned int p = pk[k];
                if (zok && (p >> 31)) {
                    const float* s = ib + (size_t)(zb + (int)(p & 0x3FFFu));
                    v = __ldg(s) + __ldg(s + VOL);
                }
            }
            fr[k] = v;
        }
    };
    auto storez = [&](int par) {
        float* tf = (float*)&tileU[par][inp][0];
        tf[(pk[0] >> 14) & 0x1FFu] = fr[0];
        tf[(pk[1] >> 14) & 0x1FFu] = fr[1];
        tf[(pk[2] >> 14) & 0x1FFu] = fr[2];
        if (has4) tf[(pk[3] >> 14) & 0x1FFu] = fr[3];
    };

    ull R0[7], R1[7];

    // prologue: plane z0-1 -> R0 (par1), plane z0 -> R1 (par0); fr = plane z0+1
    fetchz(z0 - 1);
    storez(1);
    fetchz(z0);
    __syncthreads();
    partials_only(&tileU[1][inp][0], tx, tyl, R0);
    storez(0);
    fetchz(z0 + 1);
    __syncthreads();
    partials_only(&tileU[0][inp][0], tx, tyl, R1);

    float acc = 0.0f;
    ull prevM = 0;

    auto emit = [&](int zo, ull* M, const ull* C, bool doacc) {
        const int par  = (zo + 1) & 1;   // tile buffer holding plane zo+1
        const int epar = zo & 1;         // exchange buffer for this plane
        storez(par);
        fetchz(zo + 2);
        __syncthreads();
        ull ssq = edge_step(&tileU[par][inp][0], tx, tyl, M, C);
        float mA = sqrtf(lo2(ssq) + EPS);
        float mB = sqrtf(hi2(ssq) + EPS);
        ull mag2 = mk2(mA, mB);
        if (doacc && inp == 0) {
            ull po = exch[epar ^ 1][t128];   // partner mags, plane zo-1
            float dA = lo2(prevM) - lo2(po);
            float dB = hi2(prevM) - hi2(po);
            acc = fmaf(dA, dA, acc);
            acc = fmaf(dB, dB, acc);
        }
        if (inp) exch[epar][t128] = mag2;
        prevM = mag2;
    };

#pragma unroll
    for (int i = 0; i < ZC; ++i) {
        if (i & 1) emit(z0 + i, R1, R0, true);
        else       emit(z0 + i, R0, R1, i > 0);
    }

    // epilogue: accumulate final plane z0+7
    __syncthreads();
    if (inp == 0) {
        ull po = exch[(z0 + ZC - 1) & 1][t128];
        float dA = lo2(prevM) - lo2(po);
        float dB = hi2(prevM) - hi2(po);
        acc = fmaf(dA, dA, acc);
        acc = fmaf(dB, dB, acc);
    }

    // reduction
#pragma unroll
    for (int o = 16; o; o >>= 1)
        acc += __shfl_down_sync(0xffffffffu, acc, o);
    if ((tid & 31) == 0) warpsum[tid >> 5] = acc;
    __syncthreads();
    if (tid == 0) {
        float s = 0.0f;
#pragma unroll
        for (int w = 0; w < NTHREADS / 32; ++w) s += warpsum[w];
        atomicAdd(out, s * (0.25f * INV_N));
    }
}

extern "C" void kernel_launch(void* const* d_in, const int* in_sizes, int n_in,
                              void* d_out, int out_size)
{
    const float* y  = (const float*)d_in[0];
    const float* yp = (const float*)d_in[1];
    float* out = (float*)d_out;

    gme_zero_kernel<<<1, 32>>>(out);

    dim3 grid(NX / XSPAN, NY / TYT, NB * (NZ / ZC));   // 2 x 32 x 32
    dim3 blk(TX, 8);
    gme3d_kernel<<<grid, blk>>>(y, yp, out);
}